// round 1
// baseline (speedup 1.0000x reference)
#include <cuda_runtime.h>
#include <cuda_bf16.h>
#include <cstdint>

#define D 128
#define TM 32            // nodes per GEMM block tile
#define MAX_NODES 100000

// Scratch for y = x @ W^T + b (51.2 MB). Device global (no allocation in kernel_launch).
__device__ float g_y[(size_t)MAX_NODES * D];

// ---------------------------------------------------------------------------
// GEMM: out[n, j] = sum_k x[n,k] * W[j,k] + bias[j]
// blockIdx.y == 0 -> (W, b)      -> g_y
// blockIdx.y == 1 -> (W_self, b_self) -> d_out (pre-init of accumulator)
// 128 threads; per-thread micro-tile: 4 nodes x 8 output dims (cols tx*4..+3 and 64+tx*4..+3)
// Shared: W transposed (k-major) 64KB + x tile 32x132 (padded) 16.9KB
// ---------------------------------------------------------------------------
__global__ void __launch_bounds__(128, 2)
gemm_kernel(const float* __restrict__ x,
            const float* __restrict__ W0, const float* __restrict__ b0,
            const float* __restrict__ W1, const float* __restrict__ b1,
            float* __restrict__ out0, float* __restrict__ out1,
            int n_nodes)
{
    extern __shared__ float sm[];
    float* ws = sm;                 // [128][128], ws[k*128+j] = W[j*128+k]
    float* xs = sm + D * D;         // [32][132] padded

    const float* W    = blockIdx.y ? W1 : W0;
    const float* bias = blockIdx.y ? b1 : b0;
    float* out        = blockIdx.y ? out1 : out0;

    const int tid = threadIdx.x;
    const int m0  = blockIdx.x * TM;

    // Load W transposed into shared (128 elems per thread)
    #pragma unroll 8
    for (int i = tid; i < D * D; i += 128) {
        int j = i >> 7, k = i & 127;
        ws[k * D + j] = W[i];
    }

    // Load x tile [TM x 128] vectorized (float4): TM*32 quads, 8 per thread
    #pragma unroll
    for (int i = tid; i < TM * 32; i += 128) {
        int m  = i >> 5;
        int kq = i & 31;
        int node = m0 + m;
        float4 v = make_float4(0.f, 0.f, 0.f, 0.f);
        if (node < n_nodes)
            v = reinterpret_cast<const float4*>(x + (size_t)node * D)[kq];
        float* dst = &xs[m * 132 + kq * 4];
        dst[0] = v.x; dst[1] = v.y; dst[2] = v.z; dst[3] = v.w;
    }
    __syncthreads();

    const int tx = tid & 15;   // 16 groups along N
    const int ty = tid >> 4;   // 8 groups along M (4 nodes each)

    float acc[4][8];
    #pragma unroll
    for (int i = 0; i < 4; ++i)
        #pragma unroll
        for (int j = 0; j < 8; ++j) acc[i][j] = 0.f;

    #pragma unroll 4
    for (int k = 0; k < D; ++k) {
        float4 wa = *reinterpret_cast<const float4*>(&ws[k * D + tx * 4]);
        float4 wb = *reinterpret_cast<const float4*>(&ws[k * D + 64 + tx * 4]);
        #pragma unroll
        for (int i = 0; i < 4; ++i) {
            float xv = xs[(ty * 4 + i) * 132 + k];
            acc[i][0] += xv * wa.x;
            acc[i][1] += xv * wa.y;
            acc[i][2] += xv * wa.z;
            acc[i][3] += xv * wa.w;
            acc[i][4] += xv * wb.x;
            acc[i][5] += xv * wb.y;
            acc[i][6] += xv * wb.z;
            acc[i][7] += xv * wb.w;
        }
    }

    // bias
    float4 ba = *reinterpret_cast<const float4*>(&bias[tx * 4]);
    float4 bb = *reinterpret_cast<const float4*>(&bias[64 + tx * 4]);

    #pragma unroll
    for (int i = 0; i < 4; ++i) {
        int node = m0 + ty * 4 + i;
        if (node >= n_nodes) break;
        float4 oa = make_float4(acc[i][0] + ba.x, acc[i][1] + ba.y,
                                acc[i][2] + ba.z, acc[i][3] + ba.w);
        float4 ob = make_float4(acc[i][4] + bb.x, acc[i][5] + bb.y,
                                acc[i][6] + bb.z, acc[i][7] + bb.w);
        reinterpret_cast<float4*>(out + (size_t)node * D)[tx]      = oa;
        reinterpret_cast<float4*>(out + (size_t)node * D)[16 + tx] = ob;
    }
}

// ---------------------------------------------------------------------------
// Edge scatter: one warp per edge. lane handles 4 dims via float4 gather of y
// and one vectorized red.global.add.v4.f32 into out (which holds x2).
// ---------------------------------------------------------------------------
__global__ void __launch_bounds__(256)
edge_kernel(const int* __restrict__ erow, const int* __restrict__ ecol,
            const float* __restrict__ eval_, const float* __restrict__ y,
            float* __restrict__ out, int n_edges)
{
    int e    = (int)((blockIdx.x * (unsigned)blockDim.x + threadIdx.x) >> 5);
    int lane = threadIdx.x & 31;
    if (e >= n_edges) return;

    int r   = erow[e];
    int c   = ecol[e];
    float v = eval_[e];

    float4 m = reinterpret_cast<const float4*>(y + (size_t)c * D)[lane];
    m.x *= v; m.y *= v; m.z *= v; m.w *= v;

    float* addr = out + (size_t)r * D + lane * 4;
    asm volatile("red.global.add.v4.f32 [%0], {%1, %2, %3, %4};"
                 :: "l"(addr), "f"(m.x), "f"(m.y), "f"(m.z), "f"(m.w)
                 : "memory");
}

// ---------------------------------------------------------------------------
// ReLU in place
// ---------------------------------------------------------------------------
__global__ void __launch_bounds__(256)
relu_kernel(float* __restrict__ out, int n4)
{
    int i = blockIdx.x * blockDim.x + threadIdx.x;
    if (i >= n4) return;
    float4 v = reinterpret_cast<float4*>(out)[i];
    v.x = fmaxf(v.x, 0.f);
    v.y = fmaxf(v.y, 0.f);
    v.z = fmaxf(v.z, 0.f);
    v.w = fmaxf(v.w, 0.f);
    reinterpret_cast<float4*>(out)[i] = v;
}

extern "C" void kernel_launch(void* const* d_in, const int* in_sizes, int n_in,
                              void* d_out, int out_size)
{
    const float* x     = (const float*)d_in[0];
    const int*   erow  = (const int*)  d_in[1];
    const int*   ecol  = (const int*)  d_in[2];
    const float* eval_ = (const float*)d_in[3];
    const float* W     = (const float*)d_in[4];
    const float* b     = (const float*)d_in[5];
    const float* Wself = (const float*)d_in[6];
    const float* bself = (const float*)d_in[7];
    float* out = (float*)d_out;

    int n_nodes = in_sizes[0] / D;
    int n_edges = in_sizes[1];

    float* y;
    cudaGetSymbolAddress((void**)&y, g_y);

    // GEMM: y = x W^T + b (into scratch), out = x W_self^T + b_self (accumulator init)
    size_t smem = (size_t)(D * D + TM * 132) * sizeof(float);   // 82432 B
    static bool attr_set = false;
    if (!attr_set) {
        cudaFuncSetAttribute(gemm_kernel,
                             cudaFuncAttributeMaxDynamicSharedMemorySize, (int)smem);
        attr_set = true;
    }
    dim3 grid((n_nodes + TM - 1) / TM, 2);
    gemm_kernel<<<grid, 128, smem>>>(x, W, b, Wself, bself, y, out, n_nodes);

    // Edge scatter-add: 8 warps (edges) per 256-thread block
    int warps_per_block = 256 / 32;
    int eblocks = (n_edges + warps_per_block - 1) / warps_per_block;
    edge_kernel<<<eblocks, 256>>>(erow, ecol, eval_, y, out, n_edges);

    // ReLU
    int n4 = n_nodes * D / 4;
    relu_kernel<<<(n4 + 255) / 256, 256>>>(out, n4);
}

// round 2
// speedup vs baseline: 1.2061x; 1.2061x over previous
#include <cuda_runtime.h>
#include <cuda_bf16.h>
#include <cstdint>

#define D 128
#define TM 64             // nodes per GEMM block tile
#define MAX_NODES 100000
#define MAX_EDGES 3200000

// Scratch (device globals: no runtime allocation allowed)
__device__ float  g_y[(size_t)MAX_NODES * D];        // y = x @ W^T + b   (51.2 MB)
__device__ int    g_deg[MAX_NODES];                  // degree histogram
__device__ int    g_offs[MAX_NODES + 1];             // CSR offsets
__device__ int    g_cursor[MAX_NODES];               // bump allocators
__device__ float2 g_epack[MAX_EDGES];                // {.x=val, .y=bitcast(col)} sorted by row

// ---------------------------------------------------------------------------
// GEMM: out[n, j] = sum_k x[n,k] * W[j,k] + bias[j]
// blockIdx.y == 0 -> (W, b) -> g_y ; blockIdx.y == 1 -> (W_self, b_self) -> d_out
// 256 threads; per-thread micro-tile: 4 nodes x 8 output dims.
// ---------------------------------------------------------------------------
__global__ void __launch_bounds__(256, 2)
gemm_kernel(const float* __restrict__ x,
            const float* __restrict__ W0, const float* __restrict__ b0,
            const float* __restrict__ W1, const float* __restrict__ b1,
            float* __restrict__ out0, float* __restrict__ out1,
            int n_nodes)
{
    extern __shared__ float sm[];
    float* ws = sm;                 // [128][128], ws[k*128+j] = W[j*128+k]
    float* xs = sm + D * D;         // [TM][132] padded

    const float* W    = blockIdx.y ? W1 : W0;
    const float* bias = blockIdx.y ? b1 : b0;
    float* out        = blockIdx.y ? out1 : out0;

    const int tid = threadIdx.x;
    const int m0  = blockIdx.x * TM;

    // Load W transposed into shared
    #pragma unroll 8
    for (int i = tid; i < D * D; i += 256) {
        int j = i >> 7, k = i & 127;
        ws[k * D + j] = W[i];
    }

    // Load x tile [TM x 128] as float4 (TM*32 quads, 8 per thread)
    #pragma unroll
    for (int i = tid; i < TM * 32; i += 256) {
        int m  = i >> 5;
        int kq = i & 31;
        int node = m0 + m;
        float4 v = make_float4(0.f, 0.f, 0.f, 0.f);
        if (node < n_nodes)
            v = reinterpret_cast<const float4*>(x + (size_t)node * D)[kq];
        float* dst = &xs[m * 132 + kq * 4];
        dst[0] = v.x; dst[1] = v.y; dst[2] = v.z; dst[3] = v.w;
    }
    __syncthreads();

    const int tx = tid & 15;   // 16 groups along N (8 cols each, split 2x4)
    const int ty = tid >> 4;   // 16 groups along M (4 nodes each)

    float acc[4][8];
    #pragma unroll
    for (int i = 0; i < 4; ++i)
        #pragma unroll
        for (int j = 0; j < 8; ++j) acc[i][j] = 0.f;

    #pragma unroll 4
    for (int k = 0; k < D; ++k) {
        float4 wa = *reinterpret_cast<const float4*>(&ws[k * D + tx * 4]);
        float4 wb = *reinterpret_cast<const float4*>(&ws[k * D + 64 + tx * 4]);
        #pragma unroll
        for (int i = 0; i < 4; ++i) {
            float xv = xs[(ty * 4 + i) * 132 + k];
            acc[i][0] += xv * wa.x;
            acc[i][1] += xv * wa.y;
            acc[i][2] += xv * wa.z;
            acc[i][3] += xv * wa.w;
            acc[i][4] += xv * wb.x;
            acc[i][5] += xv * wb.y;
            acc[i][6] += xv * wb.z;
            acc[i][7] += xv * wb.w;
        }
    }

    float4 ba = *reinterpret_cast<const float4*>(&bias[tx * 4]);
    float4 bb = *reinterpret_cast<const float4*>(&bias[64 + tx * 4]);

    #pragma unroll
    for (int i = 0; i < 4; ++i) {
        int node = m0 + ty * 4 + i;
        if (node >= n_nodes) break;
        float4 oa = make_float4(acc[i][0] + ba.x, acc[i][1] + ba.y,
                                acc[i][2] + ba.z, acc[i][3] + ba.w);
        float4 ob = make_float4(acc[i][4] + bb.x, acc[i][5] + bb.y,
                                acc[i][6] + bb.z, acc[i][7] + bb.w);
        reinterpret_cast<float4*>(out + (size_t)node * D)[tx]      = oa;
        reinterpret_cast<float4*>(out + (size_t)node * D)[16 + tx] = ob;
    }
}

// ---------------------------------------------------------------------------
// CSR build: histogram of rows
// ---------------------------------------------------------------------------
__global__ void __launch_bounds__(256)
hist_kernel(const int* __restrict__ erow, int n_edges)
{
    int i = blockIdx.x * blockDim.x + threadIdx.x;
    if (i < n_edges)
        atomicAdd(&g_deg[erow[i]], 1);
}

// Single-block exclusive scan (1024 threads, iterates over n)
__global__ void __launch_bounds__(1024)
scan_kernel(int n)
{
    __shared__ int warp_sums[32];
    __shared__ int s_carry;
    int tid = threadIdx.x, lane = tid & 31, wid = tid >> 5;
    if (tid == 0) s_carry = 0;
    __syncthreads();

    for (int base = 0; base < n; base += 1024) {
        int i = base + tid;
        int v = (i < n) ? g_deg[i] : 0;
        int incl = v;
        #pragma unroll
        for (int d = 1; d < 32; d <<= 1) {
            int t = __shfl_up_sync(0xffffffffu, incl, d);
            if (lane >= d) incl += t;
        }
        if (lane == 31) warp_sums[wid] = incl;
        __syncthreads();
        if (wid == 0) {
            int s = warp_sums[lane];
            #pragma unroll
            for (int d = 1; d < 32; d <<= 1) {
                int t = __shfl_up_sync(0xffffffffu, s, d);
                if (lane >= d) s += t;
            }
            warp_sums[lane] = s;
        }
        __syncthreads();
        int warp_off = (wid == 0) ? 0 : warp_sums[wid - 1];
        int excl = s_carry + warp_off + incl - v;
        if (i < n) { g_offs[i] = excl; g_cursor[i] = excl; }
        __syncthreads();
        if (tid == 0) s_carry += warp_sums[31];
        __syncthreads();
    }
    if (threadIdx.x == 0) g_offs[n] = s_carry;
}

// Scatter edges into row-sorted order (order within a row is arbitrary)
__global__ void __launch_bounds__(256)
scatter_kernel(const int* __restrict__ erow, const int* __restrict__ ecol,
               const float* __restrict__ eval_, int n_edges)
{
    int i = blockIdx.x * blockDim.x + threadIdx.x;
    if (i >= n_edges) return;
    int r = erow[i];
    int p = atomicAdd(&g_cursor[r], 1);
    g_epack[p] = make_float2(eval_[i], __int_as_float(ecol[i]));
}

// ---------------------------------------------------------------------------
// Gather: one warp per row. acc[4] per lane covers 128 dims.
// out = relu(agg + x2) where x2 was pre-stored in out by gemm_kernel.
// ---------------------------------------------------------------------------
__global__ void __launch_bounds__(256)
gather_kernel(const float* __restrict__ y, float* __restrict__ out, int n_nodes)
{
    int row  = blockIdx.x * (blockDim.x >> 5) + (threadIdx.x >> 5);
    int lane = threadIdx.x & 31;
    if (row >= n_nodes) return;

    int s = g_offs[row];
    int e = g_offs[row + 1];

    float4 acc = make_float4(0.f, 0.f, 0.f, 0.f);

    for (int base = s; base < e; base += 32) {
        int idx = base + lane;
        float2 p = make_float2(0.f, 0.f);
        if (idx < e) p = g_epack[idx];
        int cnt = min(32, e - base);

        int j = 0;
        for (; j + 4 <= cnt; j += 4) {
            float v0 = __shfl_sync(0xffffffffu, p.x, j);
            int   c0 = __float_as_int(__shfl_sync(0xffffffffu, p.y, j));
            float v1 = __shfl_sync(0xffffffffu, p.x, j + 1);
            int   c1 = __float_as_int(__shfl_sync(0xffffffffu, p.y, j + 1));
            float v2 = __shfl_sync(0xffffffffu, p.x, j + 2);
            int   c2 = __float_as_int(__shfl_sync(0xffffffffu, p.y, j + 2));
            float v3 = __shfl_sync(0xffffffffu, p.x, j + 3);
            int   c3 = __float_as_int(__shfl_sync(0xffffffffu, p.y, j + 3));

            float4 m0 = reinterpret_cast<const float4*>(y + (size_t)c0 * D)[lane];
            float4 m1 = reinterpret_cast<const float4*>(y + (size_t)c1 * D)[lane];
            float4 m2 = reinterpret_cast<const float4*>(y + (size_t)c2 * D)[lane];
            float4 m3 = reinterpret_cast<const float4*>(y + (size_t)c3 * D)[lane];

            acc.x += v0 * m0.x; acc.y += v0 * m0.y; acc.z += v0 * m0.z; acc.w += v0 * m0.w;
            acc.x += v1 * m1.x; acc.y += v1 * m1.y; acc.z += v1 * m1.z; acc.w += v1 * m1.w;
            acc.x += v2 * m2.x; acc.y += v2 * m2.y; acc.z += v2 * m2.z; acc.w += v2 * m2.w;
            acc.x += v3 * m3.x; acc.y += v3 * m3.y; acc.z += v3 * m3.z; acc.w += v3 * m3.w;
        }
        for (; j < cnt; ++j) {
            float vj = __shfl_sync(0xffffffffu, p.x, j);
            int   cj = __float_as_int(__shfl_sync(0xffffffffu, p.y, j));
            float4 m = reinterpret_cast<const float4*>(y + (size_t)cj * D)[lane];
            acc.x += vj * m.x; acc.y += vj * m.y; acc.z += vj * m.z; acc.w += vj * m.w;
        }
    }

    float4* orow = reinterpret_cast<float4*>(out + (size_t)row * D);
    float4 x2 = orow[lane];
    acc.x = fmaxf(acc.x + x2.x, 0.f);
    acc.y = fmaxf(acc.y + x2.y, 0.f);
    acc.z = fmaxf(acc.z + x2.z, 0.f);
    acc.w = fmaxf(acc.w + x2.w, 0.f);
    orow[lane] = acc;
}

extern "C" void kernel_launch(void* const* d_in, const int* in_sizes, int n_in,
                              void* d_out, int out_size)
{
    const float* x     = (const float*)d_in[0];
    const int*   erow  = (const int*)  d_in[1];
    const int*   ecol  = (const int*)  d_in[2];
    const float* eval_ = (const float*)d_in[3];
    const float* W     = (const float*)d_in[4];
    const float* b     = (const float*)d_in[5];
    const float* Wself = (const float*)d_in[6];
    const float* bself = (const float*)d_in[7];
    float* out = (float*)d_out;

    int n_nodes = in_sizes[0] / D;
    int n_edges = in_sizes[1];

    float* y;     cudaGetSymbolAddress((void**)&y, g_y);
    int*   degp;  cudaGetSymbolAddress((void**)&degp, g_deg);

    // GEMMs (y and x2)
    size_t smem = (size_t)(D * D + TM * 132) * sizeof(float);   // 99328 B
    cudaFuncSetAttribute(gemm_kernel,
                         cudaFuncAttributeMaxDynamicSharedMemorySize, (int)smem);
    dim3 grid((n_nodes + TM - 1) / TM, 2);
    gemm_kernel<<<grid, 256, smem>>>(x, W, b, Wself, bself, y, out, n_nodes);

    // CSR build
    cudaMemsetAsync(degp, 0, (size_t)n_nodes * sizeof(int));
    hist_kernel<<<(n_edges + 255) / 256, 256>>>(erow, n_edges);
    scan_kernel<<<1, 1024>>>(n_nodes);
    scatter_kernel<<<(n_edges + 255) / 256, 256>>>(erow, ecol, eval_, n_edges);

    // Gather + fuse (+x2, relu)
    int warps_per_block = 256 / 32;
    int gblocks = (n_nodes + warps_per_block - 1) / warps_per_block;
    gather_kernel<<<gblocks, 256>>>(y, out, n_nodes);
}